// round 4
// baseline (speedup 1.0000x reference)
#include <cuda_runtime.h>
#include <cstdint>

// Problem constants
#define NPTS   1048576
#define NC     32
#define NXc    64
#define Vv     (64*64*64)        // 262144
#define Bb     8
#define BV     (Bb*Vv)           // 2097152
#define HALFc  1.6f
#define RUNITc 20.0f             // fl(1/0.05f) == 20.0f — matches XLA's div->mul rewrite

// Output layout (float32, concatenated in reference tuple order)
#define OUT_PC      0
#define OUT_FEATS   (NPTS*3)                    // 3145728
#define OUT_COUNTS  (OUT_FEATS + BV*NC)         // 70254592
#define OUT_FLAG    (OUT_COUNTS + BV)           // 72351744

// Scratch: zero-initialized at module load; every kernel_launch execution
// restores it to zero (finalize kernel zeroes only touched voxels), so the
// invariant holds across graph replays. No allocation anywhere.
__device__ float g_sums[(size_t)BV * NC];   // 256 MiB
__device__ float g_counts[BV];              // 8 MiB
__device__ float g_flag[Bb];

__device__ __forceinline__ void red_add_v4(float* addr, float4 v) {
    asm volatile("red.global.add.v4.f32 [%0], {%1, %2, %3, %4};"
                 :: "l"(addr), "f"(v.x), "f"(v.y), "f"(v.z), "f"(v.w)
                 : "memory");
}

__global__ __launch_bounds__(256)
void p2v_accum(const float* __restrict__ pc,
               const float* __restrict__ feat,
               const int*   __restrict__ bid,
               float* __restrict__ out_pc) {
    int i = blockIdx.x * blockDim.x + threadIdx.x;
    if (i >= NPTS) return;

    float x = pc[3*i + 0];
    float y = pc[3*i + 1];
    float z = pc[3*i + 2];

    bool valid = (fabsf(x) <= HALFc) & (fabsf(y) <= HALFc) & (fabsf(z) <= HALFc);

    // masked point cloud
    out_pc[3*i + 0] = valid ? x : 0.0f;
    out_pc[3*i + 1] = valid ? y : 0.0f;
    out_pc[3*i + 2] = valid ? z : 0.0f;

    if (!valid) return;

    // Match XLA exactly: (p + HALF) * (1/UNIT), both ops round-to-nearest.
    // fl(1/0.05f) == 20.0f, so the reference's div-by-constant becomes *20.0f.
    int ix = (int)__fmul_rn(__fadd_rn(x, HALFc), RUNITc);
    int iy = (int)__fmul_rn(__fadd_rn(y, HALFc), RUNITc);
    int iz = (int)__fmul_rn(__fadd_rn(z, HALFc), RUNITc);
    ix = min(max(ix, 0), NXc - 1);
    iy = min(max(iy, 0), NXc - 1);
    iz = min(max(iz, 0), NXc - 1);

    int b = bid[i];
    int lin = b * Vv + ix * (64*64) + iy * 64 + iz;

    atomicAdd(&g_counts[lin], 1.0f);
    g_flag[b] = 1.0f;   // benign race: all writers store 1.0f

    const float4* f4 = reinterpret_cast<const float4*>(feat + (size_t)i * NC);
    float* dst = &g_sums[(size_t)lin * NC];
#pragma unroll
    for (int j = 0; j < NC / 4; j++) {
        float4 v = f4[j];
        red_add_v4(dst + 4*j, v);
    }
}

__global__ __launch_bounds__(256)
void p2v_finalize(float* __restrict__ out_feats,
                  float* __restrict__ out_counts,
                  float* __restrict__ out_flag) {
    int gtid = blockIdx.x * blockDim.x + threadIdx.x;
    int vox  = gtid >> 5;          // warp per voxel
    int lane = gtid & 31;          // lane = feature channel (NC == 32)
    if (vox >= BV) return;

    float c = g_counts[vox];       // broadcast load (all lanes same address)
    float o = 0.0f;
    if (c > 0.0f) {
        size_t off = (size_t)vox * NC + lane;
        float s = g_sums[off];
        o = __fdiv_rn(s, c);       // c >= 1, so max(c,1) == c; IEEE like reference
        g_sums[off] = 0.0f;        // restore scratch invariant
        if (lane == 0) g_counts[vox] = 0.0f;
    }
    out_feats[(size_t)vox * NC + lane] = o;
    if (lane == 0) out_counts[vox] = c;

    if (blockIdx.x == 0 && threadIdx.x < Bb) {
        out_flag[threadIdx.x] = g_flag[threadIdx.x];
        g_flag[threadIdx.x] = 0.0f;
    }
}

extern "C" void kernel_launch(void* const* d_in, const int* in_sizes, int n_in,
                              void* d_out, int out_size) {
    const float* pc   = (const float*)d_in[0];
    const float* feat = (const float*)d_in[1];
    const int*   bid  = (const int*)  d_in[2];
    float* out = (float*)d_out;

    // K1: per-point accumulate (4096 blocks x 256)
    p2v_accum<<<(NPTS + 255) / 256, 256>>>(pc, feat, bid, out + OUT_PC);

    // K2: warp-per-voxel finalize (2M voxels * 32 lanes / 256 threads)
    int threads_needed = BV * 32;
    p2v_finalize<<<threads_needed / 256, 256>>>(out + OUT_FEATS,
                                                out + OUT_COUNTS,
                                                out + OUT_FLAG);
}